// round 6
// baseline (speedup 1.0000x reference)
#include <cuda_runtime.h>
#include <float.h>

#define VOCAB 8000
#define C 256
#define P 8
#define BB 16
#define LL 2048
#define T 32                  // positions per block tile
#define ROWS (T + 2*P)        // 48 staged embedding rows
#define THREADS 256
#define POS_PER 16            // positions per subgroup (T / 2)
#define SMEM_BYTES ((ROWS*C + T*16 + T) * 4)   // 51328 bytes

__global__ void gnn_zero_out(float* out) {
    out[blockIdx.x * blockDim.x + threadIdx.x] = 0.0f;
}

__global__ __launch_bounds__(THREADS)
void gnn_kernel(const int* __restrict__ ids,
                const float* __restrict__ emb,
                const float* __restrict__ ew,
                const float* __restrict__ nw,
                float* __restrict__ out)
{
    extern __shared__ float smem[];
    float* rows_s = smem;                 // [ROWS][C]
    float* W_s    = smem + ROWS * C;      // [T][16]
    float* NN_s   = W_s + T * 16;         // [T]
    __shared__ int NX_s[ROWS];

    const int b  = blockIdx.y;
    const int l0 = blockIdx.x * T;
    const int* idrow = ids + b * LL;
    const int tid = threadIdx.x;

    // ---- phase 0: stage neighbor token ids ----
    if (tid < ROWS) {
        int p = l0 - P + tid;
        NX_s[tid] = (p >= 0 && p < LL) ? idrow[p] : 0;
    }
    __syncthreads();

    // ---- phase 1a: stage 48 embedding rows into SMEM (float4, coalesced, MLP=12) ----
    for (int e = tid; e < ROWS * (C / 4); e += THREADS) {
        int i  = e >> 6;          // row
        int c4 = e & 63;          // float4 column
        int nx = NX_s[i];         // row 0 of emb is all-zero
        float4 v = reinterpret_cast<const float4*>(emb + (size_t)nx * C)[c4];
        reinterpret_cast<float4*>(rows_s + i * C)[c4] = v;
    }

    // ---- phase 1b: edge-weight random DRAM gather (2 per thread) + node weights ----
    for (int e = tid; e < T * 16; e += THREADS) {
        int t = e >> 4, j = e & 15;
        int k = j + (j >= P);             // window slot 0..16, skipping center 8
        int nx = NX_s[t + k];
        int id = NX_s[t + P];
        // nx==0 -> emb row 0 all-zero -> product 0 regardless of weight value
        W_s[e] = ew[(size_t)id * VOCAB + nx];
    }
    if (tid < T) NN_s[tid] = nw[NX_s[tid + P]];
    __syncthreads();

    // ---- phase 2: register sliding window fed by cheap LDS (29-cyc latency) ----
    const int g    = tid >> 7;            // subgroup 0/1
    const int ct   = tid & 127;           // channels 2ct, 2ct+1
    const int base = g * POS_PER;
    const float2* __restrict__ r2 = (const float2*)rows_s;

    float2 win[17];
    #pragma unroll
    for (int k = 0; k < 17; k++)
        win[k] = r2[(base + k) * (C / 2) + ct];

    float acc0 = 0.f, acc1 = 0.f;

    #pragma unroll
    for (int tt = 0; tt < POS_PER; tt++) {
        const float4* wv = (const float4*)(W_s + (base + tt) * 16);
        float4 wa = wv[0], wb = wv[1], wc = wv[2], wd = wv[3];
        float nn = NN_s[base + tt];

        float m0 = -FLT_MAX, m1 = -FLT_MAX;
        #define STEP(j, wreg) { \
            float2 v = win[(tt + (j) + ((j) >= 8 ? 1 : 0)) % 17]; \
            m0 = fmaxf(m0, v.x * (wreg)); \
            m1 = fmaxf(m1, v.y * (wreg)); }
        STEP(0,  wa.x) STEP(1,  wa.y) STEP(2,  wa.z) STEP(3,  wa.w)
        STEP(4,  wb.x) STEP(5,  wb.y) STEP(6,  wb.z) STEP(7,  wb.w)
        STEP(8,  wc.x) STEP(9,  wc.y) STEP(10, wc.z) STEP(11, wc.w)
        STEP(12, wd.x) STEP(13, wd.y) STEP(14, wd.z) STEP(15, wd.w)
        #undef STEP

        float2 rn = win[(tt + 8) % 17];
        float on = 1.0f - nn;
        acc0 += on * m0 + nn * rn.x;
        acc1 += on * m1 + nn * rn.y;

        // slide: refill dead slot from SMEM (row base+tt+17), used next iter at j=16
        if (tt < POS_PER - 1)
            win[tt % 17] = r2[(base + tt + 17) * (C / 2) + ct];
    }

    atomicAdd(&out[b * C + 2 * ct + 0], acc0);
    atomicAdd(&out[b * C + 2 * ct + 1], acc1);
}

extern "C" void kernel_launch(void* const* d_in, const int* in_sizes, int n_in,
                              void* d_out, int out_size) {
    const int*   ids = (const int*)  d_in[0];
    const float* emb = (const float*)d_in[1];
    const float* ew  = (const float*)d_in[2];
    const float* nw  = (const float*)d_in[3];
    float* out = (float*)d_out;

    gnn_zero_out<<<BB, C>>>(out);   // d_out poisoned to 0xAA -> zero first

    cudaFuncSetAttribute(gnn_kernel,
                         cudaFuncAttributeMaxDynamicSharedMemorySize, SMEM_BYTES);
    dim3 grid(LL / T, BB);
    gnn_kernel<<<grid, THREADS, SMEM_BYTES>>>(ids, emb, ew, nw, out);
}

// round 7
// speedup vs baseline: 1.1764x; 1.1764x over previous
#include <cuda_runtime.h>
#include <float.h>

#define VOCAB 8000
#define C 256
#define P 8
#define BB 16
#define LL 2048
#define T 32                  // positions per block tile
#define ROWS (T + 2*P)        // 48 window-row token ids
#define THREADS 256

__global__ void gnn_zero_out(float* out) {
    out[blockIdx.x * blockDim.x + threadIdx.x] = 0.0f;
}

__global__ __launch_bounds__(THREADS)
void gnn_kernel(const int* __restrict__ ids,
                const float* __restrict__ emb,
                const float* __restrict__ ew,
                const float* __restrict__ nw,
                float* __restrict__ out)
{
    __shared__ float W_s[T * 16];   // edge weights [pos][j]
    __shared__ float NN_s[T];       // node weights
    __shared__ int   NX_s[ROWS];    // window-row token ids

    const int b  = blockIdx.y;
    const int l0 = blockIdx.x * T;
    const int* idrow = ids + b * LL;
    const int tid = threadIdx.x;

    // ---- stage token ids for the block's window rows ----
    if (tid < ROWS) {
        int p = l0 - P + tid;
        NX_s[tid] = (p >= 0 && p < LL) ? idrow[p] : 0;   // emb row 0 is all-zero
    }
    __syncthreads();

    // ---- edge-weight random DRAM gather (2 per thread, overlaps window init) ----
    #pragma unroll
    for (int e = tid; e < T * 16; e += THREADS) {
        int t = e >> 4, j = e & 15;
        int k = j + (j >= P);               // window slot, skipping center (8)
        // nx==0 -> emb row 0 all-zero -> product 0 regardless of weight value
        W_s[e] = ew[(size_t)NX_s[t + P] * VOCAB + NX_s[t + k]];
    }
    if (tid < T) NN_s[tid] = nw[NX_s[tid + P]];

    // ---- scalar register window init: 18 coalesced LDGs, MLP=18 ----
    const int ct = tid;                     // this thread's channel
    float win[17];
    #pragma unroll
    for (int k = 0; k < 17; k++)
        win[k] = emb[(size_t)NX_s[k] * C + ct];
    float nxt = emb[(size_t)NX_s[17] * C + ct];
    __syncthreads();

    float acc = 0.f;

    #pragma unroll
    for (int tt = 0; tt < T; tt++) {
        // depth-2 pipelined prefetch of row tt+18 (issued before compute)
        float nxt2 = 0.f;
        if (tt < T - 2)
            nxt2 = emb[(size_t)NX_s[tt + 18] * C + ct];

        const float4* wv = (const float4*)(W_s + tt * 16);   // broadcast LDS.128
        float4 wa = wv[0], wb = wv[1], wc = wv[2], wd = wv[3];
        float nn = NN_s[tt];

        float m0 = -FLT_MAX, m1 = -FLT_MAX;   // split chain: halves FMNMX dep depth
        #define STEP(j, wreg, m) m = fmaxf(m, win[(tt + (j) + ((j) >= 8)) % 17] * (wreg));
        STEP(0,  wa.x, m0) STEP(1,  wa.y, m1) STEP(2,  wa.z, m0) STEP(3,  wa.w, m1)
        STEP(4,  wb.x, m0) STEP(5,  wb.y, m1) STEP(6,  wb.z, m0) STEP(7,  wb.w, m1)
        STEP(8,  wc.x, m0) STEP(9,  wc.y, m1) STEP(10, wc.z, m0) STEP(11, wc.w, m1)
        STEP(12, wd.x, m0) STEP(13, wd.y, m1) STEP(14, wd.z, m0) STEP(15, wd.w, m1)
        #undef STEP
        float m = fmaxf(m0, m1);

        float rn = win[(tt + 8) % 17];
        acc += (1.0f - nn) * m + nn * rn;

        if (tt < T - 1) {                   // slide window (register renaming, free)
            win[tt % 17] = nxt;
            nxt = nxt2;
        }
    }

    atomicAdd(&out[b * C + ct], acc);
}

extern "C" void kernel_launch(void* const* d_in, const int* in_sizes, int n_in,
                              void* d_out, int out_size) {
    const int*   ids = (const int*)  d_in[0];
    const float* emb = (const float*)d_in[1];
    const float* ew  = (const float*)d_in[2];
    const float* nw  = (const float*)d_in[3];
    float* out = (float*)d_out;

    gnn_zero_out<<<BB, C>>>(out);   // d_out poisoned to 0xAA -> zero first

    dim3 grid(LL / T, BB);
    gnn_kernel<<<grid, THREADS>>>(ids, emb, ew, nw, out);
}